// round 13
// baseline (speedup 1.0000x reference)
#include <cuda_runtime.h>

#define RES     96
#define EPSF    1e-5f
#define CAPS    6144                 // smem source capacity (K ~ 4608 for this input)
#define KRAW    (RES * RES)
#define NBANDS  12
#define MAXT    36
#define GRID    148

// Global scratch (static — no cudaMalloc).
__device__ float        g_part[MAXT * 4 * 256];
__device__ unsigned int g_tick[MAXT];          // monotone tickets (replay-safe)
__device__ float4       g_ovf[KRAW];           // overflow sources (never used in practice)

// ---- f32x2 helpers ----------------------------------------------------------
__device__ __forceinline__ unsigned long long pk2(float a, float b) {
    unsigned long long r;
    asm("mov.b64 %0, {%1, %2};" : "=l"(r) : "f"(a), "f"(b));
    return r;
}
__device__ __forceinline__ void unpk2(unsigned long long v, float& a, float& b) {
    asm("mov.b64 {%0, %1}, %2;" : "=f"(a), "=f"(b) : "l"(v));
}
#define ADD2(d, a, b) asm("add.rn.f32x2 %0, %1, %2;" : "=l"(d) : "l"(a), "l"(b))
#define MUL2(d, a, b) asm("mul.rn.f32x2 %0, %1, %2;" : "=l"(d) : "l"(a), "l"(b))
#define FMA2(d, a, b, c) \
    asm("fma.rn.f32x2 %0, %1, %2, %3;" : "=l"(d) : "l"(a), "l"(b), "l"(c))

// ==============================================================================
// Single kernel, 148 blocks x 1024 threads (1 block/SM).
// Block -> (tile t = bx>>2, K-quarter h = bx&3); 34 tiles x 4 = 136 working.
// Tile = 8 rows x 32 cols (adaptive window).  Lane owns 8 rows at column j via
// 4 f32x2 accumulators (row-pairs A..D).  Per source (8 terms):
//   dens: denA full, denB/C/D incremental (t-chain, fp64-derived constants)
//   pairs (A,B),(C,D): inv = rcp(a*b); m = w*inv; accA += m*b; accB += m*a
//   -> 4 RCP / 8 terms, bursts of 2; ~26 issues / 8 terms (pre-dup smem packs).
// The 2*eps*sqrt(d2) cross term of the reference is dropped
// (relative contribution <= eps/z <= 1e-5 for interior targets).
// 4th-arriving block per tile (monotone ticket) combines quarters in fixed order.
// ==============================================================================
__global__ void __launch_bounds__(1024, 1) fused_kernel(
    const float* __restrict__ b, float* __restrict__ out)
{
    extern __shared__ unsigned long long dsm[];
    // entA: CAPS x float4 (-bi,-bi,-bj,-bj) ; entW: CAPS x float2 (w,w)
    unsigned long long* entA = dsm;                    // 2 u64 per source
    unsigned long long* entW = dsm + 2 * CAPS;         // 1 u64 per source
    __shared__ int   cnts[RES], offs[RES], sK;
    __shared__ int   tnw[NBANDS], tJ0[NBANDS], toff[NBANDS], ttab[MAXT], sWT;
    __shared__ float red[32 * 256];                    // 32 KB
    __shared__ int   sflag;

    const int tid  = threadIdx.x;
    const int wid  = tid >> 5;
    const int lane = tid & 31;

    // ---- tile geometry (input-independent) ----
    if (tid < NBANDS) {
        const int r0 = tid * 8;
        int dmin = 1000;
        #pragma unroll
        for (int r = 0; r < 8; r++) { int d = r0 + r - 48; if (d < 0) d = -d; if (d < dmin) dmin = d; }
        const int v = 2208 - dmin * dmin;
        int nw = 0, J0 = 0;
        if (v >= 0) {
            int wI = (int)sqrtf((float)v);
            while ((wI + 1) * (wI + 1) <= v) wI++;
            while (wI * wI > v) wI--;
            J0 = 47 - wI; if (J0 < 0) J0 = 0;
            nw = (2 * wI + 2 + 31) >> 5;
        }
        tnw[tid] = nw; tJ0[tid] = J0;
    }
    __syncthreads();
    if (tid == 0) {
        int s = 0;
        #pragma unroll 1
        for (int p = 0; p < NBANDS; p++) { toff[p] = s; s += tnw[p]; }
        sWT = s;
    }
    __syncthreads();
    if (tid < NBANDS)
        for (int g = 0; g < tnw[tid]; g++)
            ttab[toff[tid] + g] = tid | (g << 8) | (tJ0[tid] << 16);
    __syncthreads();

    const int WT = sWT;
    if ((int)blockIdx.x >= 4 * WT) return;

    // ---- zero smem arrays (tail safety) ----
    for (int t = tid; t < 3 * CAPS; t += 1024) dsm[t] = 0ull;

    // ---- compaction ----
    {
        const int r0 = wid * 3;
        #pragma unroll
        for (int rr = 0; rr < 3; rr++) {
            const int row = r0 + rr;
            int c = 0;
            #pragma unroll
            for (int s = 0; s < 3; s++) {
                float v = b[row * RES + s * 32 + lane];
                c += __popc(__ballot_sync(0xffffffffu, v > 0.0f));
            }
            if (lane == 0) cnts[row] = c;
        }
    }
    __syncthreads();
    if (wid == 0) {
        int a0 = cnts[lane], a1 = cnts[lane + 32], a2 = cnts[lane + 64];
        int s0 = a0, s1 = a1, s2 = a2;
        #pragma unroll
        for (int d = 1; d < 32; d <<= 1) {
            int t0 = __shfl_up_sync(0xffffffffu, s0, d); if (lane >= d) s0 += t0;
            int t1 = __shfl_up_sync(0xffffffffu, s1, d); if (lane >= d) s1 += t1;
            int t2 = __shfl_up_sync(0xffffffffu, s2, d); if (lane >= d) s2 += t2;
        }
        s1 += __shfl_sync(0xffffffffu, s0, 31);
        s2 += __shfl_sync(0xffffffffu, s1, 31);
        offs[lane]      = s0 - a0;
        offs[lane + 32] = s1 - a1;
        offs[lane + 64] = s2 - a2;
        if (lane == 31) sK = s2;
    }
    __syncthreads();
    {
        const int r0 = wid * 3;
        #pragma unroll
        for (int rr = 0; rr < 3; rr++) {
            const int row = r0 + rr;
            int p = offs[row];
            #pragma unroll
            for (int s = 0; s < 3; s++) {
                const int col = s * 32 + lane;
                float v = b[row * RES + col];
                unsigned m = __ballot_sync(0xffffffffu, v > 0.0f);
                if (v > 0.0f) {
                    int pos = p + __popc(m & ((1u << lane) - 1u));
                    if (pos < CAPS) {
                        entA[2 * pos]     = pk2(-(float)row, -(float)row);
                        entA[2 * pos + 1] = pk2(-(float)col, -(float)col);
                        entW[pos]         = pk2(v, v);
                    } else {
                        g_ovf[pos] = make_float4(-(float)row, -(float)col, v, 0.f);
                    }
                }
                p += __popc(m);
            }
        }
    }
    __syncthreads();

    // ---- rim passthrough for uncovered columns (blocks 0..11 own band bx) ----
    if (blockIdx.x < NBANDS && tid < RES) {
        const int band = blockIdx.x, j = tid;
        const int nw = tnw[band], J0p = tJ0[band];
        const bool covered = (nw > 0) && (j >= J0p) && (j < J0p + 32 * nw);
        if (!covered) {
            const int r0 = band * 8;
            #pragma unroll
            for (int r = 0; r < 8; r++)
                out[(r0 + r) * RES + j] = b[(r0 + r) * RES + j];
        }
    }

    // ---- per-block work: tile t, K-quarter h ----
    const int t    = blockIdx.x >> 2;
    const int h    = blockIdx.x & 3;
    const int info = ttab[t];
    const int band = info & 255;
    const int g    = (info >> 8) & 255;
    const int J0   = info >> 16;
    const int i0   = band * 8;

    const int   j  = J0 + 32 * g + lane;           // may be >= 96 (discarded)
    const float fj = (float)j;

    // per-lane constants (reference-faithful f32 z; fp64 combines)
    float cs[8];
    {
        const float djc = fj - 48.0f;
        const float dj2 = djc * djc;               // exact integer-valued
        #pragma unroll
        for (int r = 0; r < 8; r++) {
            float dic = (float)(i0 + r) - 48.0f;
            float z   = 48.0f - sqrtf(fmaf(dic, dic, dj2)) + EPSF;
            cs[r] = fmaf(z, z, EPSF * EPSF);
        }
    }
    const unsigned long long c01   = pk2(cs[0], cs[1]);
    const unsigned long long k0    = pk2(
        (float)(4.0 + (double)cs[2] - (double)cs[0]),
        (float)(4.0 + (double)cs[3] - (double)cs[1]));
    const unsigned long long e0    = pk2(
        (float)(8.0 + (double)cs[4] - 2.0 * (double)cs[2] + (double)cs[0]),
        (float)(8.0 + (double)cs[5] - 2.0 * (double)cs[3] + (double)cs[1]));
    const unsigned long long e1    = pk2(
        (float)(8.0 + (double)cs[6] - 2.0 * (double)cs[4] + (double)cs[2]),
        (float)(8.0 + (double)cs[7] - 2.0 * (double)cs[5] + (double)cs[3]));
    const unsigned long long four2 = pk2(4.0f, 4.0f);
    const unsigned long long fi01  = pk2((float)i0, (float)(i0 + 1));
    const unsigned long long fj2   = pk2(fj, fj);

    const int K  = sK;
    const int sa = (K * h) >> 2;
    const int sb = (K * (h + 1)) >> 2;
    const int sbm = sb < CAPS ? sb : CAPS;

    unsigned long long acc0 = pk2(0.f, 0.f), acc1 = acc0, acc2 = acc0, acc3 = acc0;

    // ---- main loop: 8 rows per lane, incremental dens, paired reciprocals ----
    #pragma unroll 4
    for (int s = sa + wid; s < sbm; s += 32) {
        unsigned long long Ai, Aj, W2;
        asm("ld.shared.v2.u64 {%0, %1}, [%2];"
            : "=l"(Ai), "=l"(Aj)
            : "r"((unsigned)__cvta_generic_to_shared(&entA[2 * s])));
        asm("ld.shared.u64 %0, [%1];"
            : "=l"(W2)
            : "r"((unsigned)__cvta_generic_to_shared(&entW[s])));

        unsigned long long di01, dj2, u, dA, dB, dC, dD, tq;
        ADD2(di01, fi01, Ai);
        ADD2(dj2,  fj2,  Aj);
        FMA2(u, dj2, dj2, c01);
        FMA2(dA, di01, di01, u);
        FMA2(tq, di01, four2, k0);
        ADD2(dB, dA, tq);
        ADD2(tq, tq, e0);
        ADD2(dC, dB, tq);
        ADD2(tq, tq, e1);
        ADD2(dD, dC, tq);

        unsigned long long P, inv, m;
        float pl, ph, il, ih;
        MUL2(P, dA, dB);
        unpk2(P, pl, ph);
        asm("rcp.approx.ftz.f32 %0, %1;" : "=f"(il) : "f"(pl));
        asm("rcp.approx.ftz.f32 %0, %1;" : "=f"(ih) : "f"(ph));
        inv = pk2(il, ih);
        MUL2(m, W2, inv);
        FMA2(acc0, m, dB, acc0);               // w/denA
        FMA2(acc1, m, dA, acc1);               // w/denB

        MUL2(P, dC, dD);
        unpk2(P, pl, ph);
        asm("rcp.approx.ftz.f32 %0, %1;" : "=f"(il) : "f"(pl));
        asm("rcp.approx.ftz.f32 %0, %1;" : "=f"(ih) : "f"(ph));
        inv = pk2(il, ih);
        MUL2(m, W2, inv);
        FMA2(acc2, m, dD, acc2);               // w/denC
        FMA2(acc3, m, dC, acc3);               // w/denD
    }

    // ---- overflow fallback (never taken for this dataset; keeps correctness)
    float xacc[8] = {0,0,0,0,0,0,0,0};
    if (sb > CAPS) {
        const int lo = sa > CAPS ? sa : CAPS;
        for (int s = lo + wid; s < sb; s += 32) {
            float4 e = g_ovf[s];               // (-bi, -bj, w, 0)
            float dj = fj + e.y;
            #pragma unroll
            for (int r = 0; r < 8; r++) {
                float di  = (float)(i0 + r) + e.x;
                float den = fmaf(di, di, fmaf(dj, dj, cs[r]));
                float iv;
                asm("rcp.approx.ftz.f32 %0, %1;" : "=f"(iv) : "f"(den));
                xacc[r] = fmaf(e.z, iv, xacc[r]);
            }
        }
    }

    // ---- intra-block reduction: 32 warps -> 256 partials ----
    {
        float lo, hi;
        unpk2(acc0, lo, hi);
        red[wid * 256 +   0 + lane] = lo + xacc[0];
        red[wid * 256 +  32 + lane] = hi + xacc[1];
        unpk2(acc1, lo, hi);
        red[wid * 256 +  64 + lane] = lo + xacc[2];
        red[wid * 256 +  96 + lane] = hi + xacc[3];
        unpk2(acc2, lo, hi);
        red[wid * 256 + 128 + lane] = lo + xacc[4];
        red[wid * 256 + 160 + lane] = hi + xacc[5];
        unpk2(acc3, lo, hi);
        red[wid * 256 + 192 + lane] = lo + xacc[6];
        red[wid * 256 + 224 + lane] = hi + xacc[7];
    }
    __syncthreads();

    if (tid < 256) {
        float part = 0.0f;
        #pragma unroll 8
        for (int w = 0; w < 32; w++) part += red[w * 256 + tid];
        g_part[(t * 4 + h) * 256 + tid] = part;
    }
    __threadfence();
    __syncthreads();
    if (tid == 0) {
        unsigned old = atomicAdd(&g_tick[t], 1u);
        sflag = ((old & 3u) == 3u);            // 4th arrival this launch
        __threadfence();
    }
    __syncthreads();

    // ---- 4th-arriving block combines the 4 quarters (fixed order) & writes ----
    if (sflag && tid < 256) {
        float s = 0.0f;
        #pragma unroll
        for (int h2 = 0; h2 < 4; h2++)
            s += __ldcg(&g_part[(t * 4 + h2) * 256 + tid]);
        const int row = i0 + (tid >> 5);
        const int col = J0 + 32 * g + (tid & 31);
        if (col < RES) {
            const int di = row - 48, dj = col - 48;
            const float bv = b[row * RES + col];
            out[row * RES + col] = (di * di + dj * dj >= 2209) ? bv : s;
        }
    }
}

// ------------------------------------------------------------------------------
extern "C" void kernel_launch(void* const* d_in, const int* in_sizes, int n_in,
                              void* d_out, int out_size) {
    (void)in_sizes; (void)n_in; (void)out_size;
    const float* b   = (const float*)d_in[0];
    float*       out = (float*)d_out;

    const int smem_bytes = 3 * CAPS * 8;       // 147456
    cudaFuncSetAttribute(fused_kernel,
                         cudaFuncAttributeMaxDynamicSharedMemorySize, smem_bytes);

    fused_kernel<<<GRID, 1024, smem_bytes>>>(b, out);
}

// round 14
// speedup vs baseline: 1.0083x; 1.0083x over previous
#include <cuda_runtime.h>

#define RES    96
#define EPSF   1e-5f
#define CAPS   (RES * RES)           // 9216 per-source records
#define CAPP   (CAPS / 2)            // 4608 source-pair records
#define NTILE  144                   // 48 i-pairs x 3 windows
#define GRID   148
#define NWG    (GRID * 32)           // 4736 warps
#define MAXREC 8

// Global scratch (static — no cudaMalloc).
__device__ float        g_part[NWG * MAXREC * 64];
__device__ unsigned int g_tick[NTILE];          // monotone tickets (replay-safe)

// ---- f32x2 helpers ----------------------------------------------------------
__device__ __forceinline__ unsigned long long pk2(float a, float b) {
    unsigned long long r;
    asm("mov.b64 %0, {%1, %2};" : "=l"(r) : "f"(a), "f"(b));
    return r;
}
__device__ __forceinline__ void unpk2(unsigned long long v, float& a, float& b) {
    asm("mov.b64 {%0, %1}, %2;" : "=f"(a), "=f"(b) : "l"(v));
}
#define ADD2(d, a, b) asm("add.rn.f32x2 %0, %1, %2;" : "=l"(d) : "l"(a), "l"(b))
#define MUL2(d, a, b) asm("mul.rn.f32x2 %0, %1, %2;" : "=l"(d) : "l"(a), "l"(b))
#define FMA2(d, a, b, c) \
    asm("fma.rn.f32x2 %0, %1, %2, %3;" : "=l"(d) : "l"(a), "l"(b), "l"(c))

// window start for i-pair pp (input-independent)
__device__ __forceinline__ int pair_J0(int pp) {
    const int a0 = abs(2 * pp - 48);
    const int a1 = abs(2 * pp + 1 - 48);
    const int dmin = a0 < a1 ? a0 : a1;
    int s_ = 2208 - dmin * dmin; if (s_ < 0) s_ = 0;
    const int wmax = (int)sqrtf((float)s_) + 1;     // over-estimate: safe
    int J0 = 48 - wmax; if (J0 < 0) J0 = 0;
    return J0;
}

// ==============================================================================
// Single kernel, 148 blocks x 1024 threads.
// Phase 1: per-block compaction of positive boundary values into SMEM:
//          entA[s] = (-bi,-bi,-bj,-bj), entW[p] = (w0,w0,w1,w1)  (R10 layout).
// Phase 2: FLAT BALANCED loop — item = (tile, source-pair); each warp owns a
//          contiguous span of L = ceil(144*Kp/4736) ~ 71 items (<= MAXREC tile
//          fragments), accumulating with the paired-reciprocal f32x2 body:
//            a=den(s0), b=den(s1); acc += (w0*b+w1*a)*rcp(a*b)   (full f32)
//          The 2*eps*sqrt(d2) cross term of the reference is dropped
//          (relative contribution <= eps/z <= 1e-5 for interior targets).
// Phase 3: warp publishes each 64-float record to gmem, fences, tickets the
//          tile; the arrival completing the tile's contributor count C(t)
//          (closed-form) sums records wlo..whi in fixed order and writes the
//          64 outputs with the exact integer rim select.  No grid barrier.
// ==============================================================================
__global__ void __launch_bounds__(1024, 1) fused_kernel(
    const float* __restrict__ b, float* __restrict__ out)
{
    extern __shared__ float4 sm[];
    float4* entA = sm;                    // CAPS  float4
    float4* entW = sm + CAPS;             // CAPP  float4
    __shared__ int cnts[RES];
    __shared__ int offs[RES];
    __shared__ int sK;

    const int tid  = threadIdx.x;
    const int wid  = tid >> 5;
    const int lane = tid & 31;

    // ---- Phase 0: zero packed arrays (pair-tail safety) ----
    for (int t = tid; t < CAPS + CAPP; t += 1024)
        sm[t] = make_float4(0.f, 0.f, 0.f, 0.f);

    // ---- Phase 1: compaction (row-major deterministic order) ----
    {
        const int r0 = wid * 3;
        #pragma unroll
        for (int rr = 0; rr < 3; rr++) {
            const int row = r0 + rr;
            int c = 0;
            #pragma unroll
            for (int s = 0; s < 3; s++) {
                float v = b[row * RES + s * 32 + lane];
                c += __popc(__ballot_sync(0xffffffffu, v > 0.0f));
            }
            if (lane == 0) cnts[row] = c;
        }
    }
    __syncthreads();
    if (wid == 0) {                       // exclusive prefix over 96 counts
        int a0 = cnts[lane], a1 = cnts[lane + 32], a2 = cnts[lane + 64];
        int s0 = a0, s1 = a1, s2 = a2;
        #pragma unroll
        for (int d = 1; d < 32; d <<= 1) {
            int t0 = __shfl_up_sync(0xffffffffu, s0, d); if (lane >= d) s0 += t0;
            int t1 = __shfl_up_sync(0xffffffffu, s1, d); if (lane >= d) s1 += t1;
            int t2 = __shfl_up_sync(0xffffffffu, s2, d); if (lane >= d) s2 += t2;
        }
        s1 += __shfl_sync(0xffffffffu, s0, 31);
        s2 += __shfl_sync(0xffffffffu, s1, 31);
        offs[lane]      = s0 - a0;
        offs[lane + 32] = s1 - a1;
        offs[lane + 64] = s2 - a2;
        if (lane == 31) sK = s2;
    }
    __syncthreads();
    {
        const int r0 = wid * 3;
        #pragma unroll
        for (int rr = 0; rr < 3; rr++) {
            const int row = r0 + rr;
            int p = offs[row];
            #pragma unroll
            for (int s = 0; s < 3; s++) {
                const int col = s * 32 + lane;
                float v = b[row * RES + col];
                unsigned m = __ballot_sync(0xffffffffu, v > 0.0f);
                if (v > 0.0f) {
                    int pos = p + __popc(m & ((1u << lane) - 1u));
                    entA[pos] = make_float4(-(float)row, -(float)row,
                                            -(float)col, -(float)col);
                    float* wp = reinterpret_cast<float*>(&entW[pos >> 1]);
                    const int o = (pos & 1) * 2;
                    wp[o]     = v;
                    wp[o + 1] = v;
                }
                p += __popc(m);
            }
        }
    }
    __syncthreads();

    const int K  = sK;
    const int Kp = (K + 1) >> 1;

    // ---- rim passthrough (+ K==0 interior zeros) : blocks 0..47 own pair bx
    if (blockIdx.x < 48 && tid < RES) {
        const int pp = blockIdx.x, j = tid;
        const int J0 = pair_J0(pp);
        const bool covered = (j >= J0) && (j < J0 + 96) && (Kp > 0);
        if (!covered) {
            const int i0 = 2 * pp;
            #pragma unroll
            for (int r = 0; r < 2; r++) {
                const int di = i0 + r - 48, dj = j - 48;
                const float bv = b[(i0 + r) * RES + j];
                out[(i0 + r) * RES + j] =
                    (di * di + dj * dj >= 2209) ? bv : 0.0f;
            }
        }
    }
    if (Kp == 0) return;

    // ---- Phase 2: flat balanced loop ----
    const int total = NTILE * Kp;
    const int L     = (total + NWG - 1) / NWG;
    const int wg    = blockIdx.x * 32 + wid;
    int q0 = wg * L; if (q0 > total) q0 = total;
    int q1 = q0 + L; if (q1 > total) q1 = total;
    const int tfirst = (q0 < q1) ? (q0 / Kp) : -1;
    int rec = 0;

    while (q0 < q1 && rec < MAXREC) {
        const int t  = q0 / Kp;
        const int pa = q0 - t * Kp;
        int pb = pa + (q1 - q0); if (pb > Kp) pb = Kp;

        // tile constants
        const int pp = t / 3;
        const int g  = t % 3;
        const int J0 = pair_J0(pp);
        const int i0 = 2 * pp;
        const float fi0 = (float)i0;
        const float fj  = (float)(J0 + 32 * g + lane);   // may be >= 96 (discarded)

        const float dic0 = fi0 - 48.0f;
        const float dic1 = dic0 + 1.0f;
        const float djc  = fj - 48.0f;
        const float z0 = 48.0f - sqrtf(fmaf(dic0, dic0, djc * djc)) + EPSF;
        const float z1 = 48.0f - sqrtf(fmaf(dic1, dic1, djc * djc)) + EPSF;
        const unsigned long long c01  = pk2(fmaf(z0, z0, EPSF * EPSF),
                                            fmaf(z1, z1, EPSF * EPSF));
        const unsigned long long fi01 = pk2(fi0, fi0 + 1.0f);
        const unsigned long long fj2  = pk2(fj, fj);

        unsigned long long acc = pk2(0.0f, 0.0f);
        #pragma unroll 4
        for (int p = pa; p < pb; p++) {
            unsigned long long A0i, A0j, A1i, A1j, W0, W1;
            asm("ld.shared.v2.u64 {%0, %1}, [%2];"
                : "=l"(A0i), "=l"(A0j)
                : "r"((unsigned)__cvta_generic_to_shared(&entA[2 * p])));
            asm("ld.shared.v2.u64 {%0, %1}, [%2];"
                : "=l"(A1i), "=l"(A1j)
                : "r"((unsigned)__cvta_generic_to_shared(&entA[2 * p + 1])));
            asm("ld.shared.v2.u64 {%0, %1}, [%2];"
                : "=l"(W0), "=l"(W1)
                : "r"((unsigned)__cvta_generic_to_shared(&entW[p])));

            unsigned long long di0, dj0, u0, a, di1, dj1, u1, bb;
            ADD2(di0, fi01, A0i);
            ADD2(dj0, fj2,  A0j);
            FMA2(u0, dj0, dj0, c01);
            FMA2(a,  di0, di0, u0);
            ADD2(di1, fi01, A1i);
            ADD2(dj1, fj2,  A1j);
            FMA2(u1, dj1, dj1, c01);
            FMA2(bb, di1, di1, u1);

            unsigned long long P, m, num;
            MUL2(P, a, bb);
            MUL2(m, W0, bb);
            FMA2(num, W1, a, m);

            float pl, ph, il, ih;
            unpk2(P, pl, ph);
            asm("rcp.approx.ftz.f32 %0, %1;" : "=f"(il) : "f"(pl));
            asm("rcp.approx.ftz.f32 %0, %1;" : "=f"(ih) : "f"(ph));
            const unsigned long long inv = pk2(il, ih);
            FMA2(acc, num, inv, acc);
        }

        float f0, f1;
        unpk2(acc, f0, f1);
        const int slot = wg * MAXREC + rec;
        g_part[slot * 64 + lane]      = f0;
        g_part[slot * 64 + 32 + lane] = f1;

        rec++;
        q0 += pb - pa;
    }

    // ---- Phase 3: publish + per-tile ticket + finish (warp-granular) ----
    if (rec > 0) {
        __threadfence();                           // publish this warp's records
        __syncwarp();

        const int nrec = rec;
        for (int r = 0; r < nrec; r++) {
            const int t = tfirst + r;
            // contributor range for tile t (closed-form, launch-invariant)
            const int wlo = (t * Kp) / L;
            const int whi = ((t + 1) * Kp - 1) / L;
            const unsigned C = (unsigned)(whi - wlo + 1);

            unsigned last = 0;
            if (lane == 0) {
                unsigned old = atomicAdd(&g_tick[t], 1u);
                last = ((old % C) == C - 1u);
            }
            last = __shfl_sync(0xffffffffu, last, 0);
            if (!last) continue;

            __threadfence();                       // acquire side
            float s0 = 0.0f, s1 = 0.0f;
            #pragma unroll 4
            for (int w2 = wlo; w2 <= whi; w2++) {
                const int tA = (w2 * L) / Kp;
                const int sl = w2 * MAXREC + (t - tA);
                s0 += __ldcg(&g_part[sl * 64 + lane]);
                s1 += __ldcg(&g_part[sl * 64 + 32 + lane]);
            }

            const int pp = t / 3;
            const int g  = t % 3;
            const int J0 = pair_J0(pp);
            const int i0 = 2 * pp;
            const int jj = J0 + 32 * g + lane;
            if (jj < RES) {
                const int dj = jj - 48;
                {
                    const int di = i0 - 48;
                    const float bv = b[i0 * RES + jj];
                    out[i0 * RES + jj] =
                        (di * di + dj * dj >= 2209) ? bv : s0;
                }
                {
                    const int di = i0 + 1 - 48;
                    const float bv = b[(i0 + 1) * RES + jj];
                    out[(i0 + 1) * RES + jj] =
                        (di * di + dj * dj >= 2209) ? bv : s1;
                }
            }
        }
    }
}

// ------------------------------------------------------------------------------
extern "C" void kernel_launch(void* const* d_in, const int* in_sizes, int n_in,
                              void* d_out, int out_size) {
    (void)in_sizes; (void)n_in; (void)out_size;
    const float* b   = (const float*)d_in[0];
    float*       out = (float*)d_out;

    const int smem_bytes = (CAPS + CAPP) * (int)sizeof(float4);  // 221184
    cudaFuncSetAttribute(fused_kernel,
                         cudaFuncAttributeMaxDynamicSharedMemorySize, smem_bytes);

    fused_kernel<<<GRID, 1024, smem_bytes>>>(b, out);
}

// round 15
// speedup vs baseline: 1.1089x; 1.0999x over previous
#include <cuda_runtime.h>
#include <cuda_fp16.h>

#define RES     96
#define CENTERF 48.0f
#define EPSF    1e-5f
#define KPMAX   (RES * RES / 2)      // 4608 packed 2-source records
#define RIM2    2209.0f
#define NTW     144                  // 48 i-pairs x 3 windows

// Global scratch (static — no cudaMalloc).
__device__ uint4        g_ent[KPMAX];           // f16 pair records
__device__ int          g_K;                    // compacted source count
__device__ float        g_part[NTW * 2 * 64];   // 2 K-halves x 64 targets / tile
__device__ unsigned int g_tick[NTW];            // monotone tickets (replay-safe)

// ==============================================================================
// Prekernel: 1 block x 1024 threads.  Deterministic ballot compaction of the
// strictly-positive boundary values into g_ent as f16 pair-records:
//   record k = sources (2k, 2k+1): { h2(-bi0,-bi1), h2(bj0,bj1), h2(w0,w1), 0 }
// Array pre-zeroed each launch (odd-K tail term contributes exactly 0).
// ==============================================================================
__global__ void __launch_bounds__(1024) compact_kernel(const float* __restrict__ b)
{
    __shared__ int cnts[RES];
    __shared__ int offs[RES];
    const int tid  = threadIdx.x;
    const int wid  = tid >> 5;
    const int lane = tid & 31;

    for (int t = tid; t < KPMAX; t += 1024)
        g_ent[t] = make_uint4(0u, 0u, 0u, 0u);

    {   // per-row positive counts (warp w owns rows 3w..3w+2)
        const int r0 = wid * 3;
        #pragma unroll
        for (int rr = 0; rr < 3; rr++) {
            const int row = r0 + rr;
            int c = 0;
            #pragma unroll
            for (int s = 0; s < 3; s++) {
                float v = b[row * RES + s * 32 + lane];
                c += __popc(__ballot_sync(0xffffffffu, v > 0.0f));
            }
            if (lane == 0) cnts[row] = c;
        }
    }
    __syncthreads();
    if (wid == 0) {                  // exclusive prefix over 96 row counts
        int a0 = cnts[lane], a1 = cnts[lane + 32], a2 = cnts[lane + 64];
        int s0 = a0, s1 = a1, s2 = a2;
        #pragma unroll
        for (int d = 1; d < 32; d <<= 1) {
            int t0 = __shfl_up_sync(0xffffffffu, s0, d); if (lane >= d) s0 += t0;
            int t1 = __shfl_up_sync(0xffffffffu, s1, d); if (lane >= d) s1 += t1;
            int t2 = __shfl_up_sync(0xffffffffu, s2, d); if (lane >= d) s2 += t2;
        }
        s1 += __shfl_sync(0xffffffffu, s0, 31);
        s2 += __shfl_sync(0xffffffffu, s1, 31);
        offs[lane]      = s0 - a0;
        offs[lane + 32] = s1 - a1;
        offs[lane + 64] = s2 - a2;
        if (lane == 31) g_K = s2;
    }
    __syncthreads();
    {   // scatter: element pos -> record pos>>1, half-lane pos&1
        const int r0 = wid * 3;
        #pragma unroll
        for (int rr = 0; rr < 3; rr++) {
            const int row = r0 + rr;
            int p = offs[row];
            #pragma unroll
            for (int s = 0; s < 3; s++) {
                const int col = s * 32 + lane;
                float v = b[row * RES + col];
                unsigned m = __ballot_sync(0xffffffffu, v > 0.0f);
                if (v > 0.0f) {
                    int pos = p + __popc(m & ((1u << lane) - 1u));
                    __half* hp = reinterpret_cast<__half*>(&g_ent[pos >> 1]);
                    const int o = pos & 1;
                    hp[0 + o] = __float2half_rn(-(float)row);
                    hp[2 + o] = __float2half_rn((float)col);
                    hp[4 + o] = __float2half_rn(v);
                }
                p += __popc(m);
            }
        }
    }
}

// ==============================================================================
// Compute kernel: 288 blocks = 48 i-pairs x 3 adaptive windows x 2 K-halves.
// __launch_bounds__(1024, 2) -> 2 blocks/SM, 64 warps/SM (regs <= 32).
// NO smem staging: records read via uniform __ldg from the L2-resident list.
// Per record per lane -> 4 terms (2 sources x 2 rows), R12-proven f16 body:
//   dj2=fj2-bj2  di0=fi0+nbi2  di1=fi1+nbi2
//   den0=hfma2(di0,di0,hfma2(dj2,dj2,c0))  den1=hfma2(di1,di1,hfma2(dj2,dj2,c1))
//   acc0+=w2*h2rcp(den0)  acc1+=w2*h2rcp(den1)   (flushed to f32 every 4)
// The 2*eps*sqrt(d2) cross term of the reference is dropped
// (relative contribution <= eps/z <= 1e-5 for interior targets).
// K-halves combined by the 2nd-arriving block per tile (fixed order).
// ==============================================================================
__global__ void __launch_bounds__(1024, 2) potential_kernel(
    const float* __restrict__ b, float* __restrict__ out)
{
    __shared__ float red[32 * 64];
    __shared__ int   sflag;

    const int tid  = threadIdx.x;
    const int wid  = tid >> 5;
    const int lane = tid & 31;

    // ---- window placement ----
    const int pp  = blockIdx.x / 6;               // i-pair 0..47
    const int rem = blockIdx.x % 6;
    const int g   = rem >> 1;                     // window 0..2
    const int h   = rem & 1;                      // K-half
    const int tw  = pp * 3 + g;                   // tile id 0..143
    const int i0  = 2 * pp;

    const int a0i = abs(i0 - 48);
    const int a1i = abs(i0 + 1 - 48);
    const int dmin = a0i < a1i ? a0i : a1i;
    int s_ = 2208 - dmin * dmin; if (s_ < 0) s_ = 0;
    const int wmax = (int)sqrtf((float)s_) + 1;   // over-estimate: safe
    int J0 = 48 - wmax; if (J0 < 0) J0 = 0;

    const int j   = J0 + 32 * g + lane;           // may exceed 95 (guarded)
    const float fi0 = (float)i0;
    const float fj  = (float)j;

    const float dic0 = fi0 - CENTERF;
    const float dic1 = dic0 + 1.0f;
    const float djc  = fj - CENTERF;
    const float r2_0 = dic0 * dic0 + djc * djc;   // exact integer-valued
    const float r2_1 = dic1 * dic1 + djc * djc;
    const float z0 = CENTERF - sqrtf(r2_0) + EPSF;
    const float z1 = CENTERF - sqrtf(r2_1) + EPSF;
    const float c00 = fmaf(z0, z0, EPSF * EPSF);
    const float c01 = fmaf(z1, z1, EPSF * EPSF);

    const __half2 c0_2  = __half2half2(__float2half_rn(c00));
    const __half2 c1_2  = __half2half2(__float2half_rn(c01));
    const __half2 fi0_2 = __half2half2(__float2half_rn(fi0));
    const __half2 fi1_2 = __half2half2(__float2half_rn(fi0 + 1.0f));
    const __half2 fj2   = __half2half2(__float2half_rn(fj));
    const __half2 zero2 = __floats2half2_rn(0.0f, 0.0f);

    const bool allrim = __all_sync(0xffffffffu,
                                   (r2_0 >= RIM2) && (r2_1 >= RIM2));
    const int Kp = (g_K + 1) >> 1;
    const int pa = (Kp * h) >> 1;
    const int pb = (Kp * (h + 1)) >> 1;
    float f0 = 0.0f, f1 = 0.0f;

    // ---- main loop over this block's K-half (uniform LDG.128, L2-hot) ----
    if (!allrim) {
        __half2 acc0 = zero2, acc1 = zero2;
        const int n = pb - pa;
        const int nfull = (n > wid) ? (n - wid + 31) / 32 : 0;
        const int nb4 = nfull >> 2;
        const uint4* pe = g_ent + pa + wid;

        for (int b4 = 0; b4 < nb4; b4++) {
            #pragma unroll
            for (int u = 0; u < 4; u++) {
                uint4 e = __ldg(&pe[u * 32]);
                __half2 nbi2 = *reinterpret_cast<__half2*>(&e.x);
                __half2 bj2  = *reinterpret_cast<__half2*>(&e.y);
                __half2 w2   = *reinterpret_cast<__half2*>(&e.z);
                __half2 dj2  = __hsub2(fj2, bj2);
                __half2 di0  = __hadd2(fi0_2, nbi2);
                __half2 di1  = __hadd2(fi1_2, nbi2);
                __half2 den0 = __hfma2(di0, di0, __hfma2(dj2, dj2, c0_2));
                __half2 den1 = __hfma2(di1, di1, __hfma2(dj2, dj2, c1_2));
                acc0 = __hfma2(w2, h2rcp(den0), acc0);
                acc1 = __hfma2(w2, h2rcp(den1), acc1);
            }
            pe += 128;
            f0 += __low2float(acc0) + __high2float(acc0);
            f1 += __low2float(acc1) + __high2float(acc1);
            acc0 = zero2; acc1 = zero2;
        }
        for (int r = nb4 * 4; r < nfull; r++) {
            uint4 e = __ldg(pe); pe += 32;
            __half2 nbi2 = *reinterpret_cast<__half2*>(&e.x);
            __half2 bj2  = *reinterpret_cast<__half2*>(&e.y);
            __half2 w2   = *reinterpret_cast<__half2*>(&e.z);
            __half2 dj2  = __hsub2(fj2, bj2);
            __half2 di0  = __hadd2(fi0_2, nbi2);
            __half2 di1  = __hadd2(fi1_2, nbi2);
            __half2 den0 = __hfma2(di0, di0, __hfma2(dj2, dj2, c0_2));
            __half2 den1 = __hfma2(di1, di1, __hfma2(dj2, dj2, c1_2));
            acc0 = __hfma2(w2, h2rcp(den0), acc0);
            acc1 = __hfma2(w2, h2rcp(den1), acc1);
        }
        f0 += __low2float(acc0) + __high2float(acc0);
        f1 += __low2float(acc1) + __high2float(acc1);
    }

    red[wid * 64 + lane]      = f0;
    red[wid * 64 + 32 + lane] = f1;
    __syncthreads();

    // ---- block reduce -> global partial ----
    if (tid < 64) {
        float s = 0.0f;
        #pragma unroll 8
        for (int w = 0; w < 32; w++) s += red[w * 64 + tid];
        g_part[(tw * 2 + h) * 64 + tid] = s;
    }

    // rim passthrough for uncovered columns j < J0 (one block per pair)
    if (g == 0 && h == 0 && tid < RES && tid < J0) {
        out[i0 * RES + tid]       = b[i0 * RES + tid];
        out[(i0 + 1) * RES + tid] = b[(i0 + 1) * RES + tid];
    }

    __threadfence();                              // publish partial (gpu scope)
    __syncthreads();
    if (tid == 0) {
        unsigned old = atomicAdd(&g_tick[tw], 1u);
        sflag = ((old & 1u) == 1u);               // 2nd arrival this launch
        __threadfence();                          // acquire side
    }
    __syncthreads();

    // ---- 2nd-arriving block combines both K-halves (fixed order) & writes ----
    if (sflag && tid < 64) {
        float s = __ldcg(&g_part[(tw * 2 + 0) * 64 + tid])
                + __ldcg(&g_part[(tw * 2 + 1) * 64 + tid]);
        const int k  = tid >> 5;
        const int l  = tid & 31;
        const int ii = i0 + k;
        const int jj = J0 + 32 * g + l;
        if (jj < RES) {
            const int di = ii - 48, dj = jj - 48;
            const float bv = b[ii * RES + jj];
            out[ii * RES + jj] = (di * di + dj * dj >= 2209) ? bv : s;
        }
    }
}

// ---------------------------------------------------------------------------
extern "C" void kernel_launch(void* const* d_in, const int* in_sizes, int n_in,
                              void* d_out, int out_size) {
    (void)in_sizes; (void)n_in; (void)out_size;
    const float* b   = (const float*)d_in[0];
    float*       out = (float*)d_out;

    compact_kernel<<<1, 1024>>>(b);
    potential_kernel<<<288, 1024>>>(b, out);
}

// round 16
// speedup vs baseline: 1.6255x; 1.4658x over previous
#include <cuda_runtime.h>

#define RES     96
#define CENTERF 48.0f
#define EPSF    1e-5f
#define NWARPS  32
#define RIM2    2209.0f

#define CAPS    (RES * RES)          // per-source entA capacity
#define CAPP    ((CAPS + 1) / 2)     // source-pair capacity (entW)

// ---- f32x2 helpers ----------------------------------------------------------
__device__ __forceinline__ unsigned long long pk2(float a, float b) {
    unsigned long long r;
    asm("mov.b64 %0, {%1, %2};" : "=l"(r) : "f"(a), "f"(b));
    return r;
}
__device__ __forceinline__ void unpk2(unsigned long long v, float& a, float& b) {
    asm("mov.b64 {%0, %1}, %2;" : "=f"(a), "=f"(b) : "l"(v));
}
#define ADD2(d, a, b) asm("add.rn.f32x2 %0, %1, %2;" : "=l"(d) : "l"(a), "l"(b))
#define MUL2(d, a, b) asm("mul.rn.f32x2 %0, %1, %2;" : "=l"(d) : "l"(a), "l"(b))
#define FMA2(d, a, b, c) \
    asm("fma.rn.f32x2 %0, %1, %2, %3;" : "=l"(d) : "l"(a), "l"(b), "l"(c))
// paired reciprocal on a 64-bit register pair (ptxas elides the virtual movs)
#define RCP2(d, s) asm("{.reg .f32 lo, hi;\n\t" \
                       "mov.b64 {lo, hi}, %1;\n\t" \
                       "rcp.approx.ftz.f32 lo, lo;\n\t" \
                       "rcp.approx.ftz.f32 hi, hi;\n\t" \
                       "mov.b64 %0, {lo, hi};}" : "=l"(d) : "l"(s))

// ---------------------------------------------------------------------------
// Single kernel (R10 structure, slimmed inner loop).
// Grid: 144 = 48 i-pairs x 3 adaptive 32-wide j-windows.  Block: 1024 threads,
// 32 warps splitting the source-pair list (72 iters/warp at K~4608).
//
// SMEM: entA[s] = float4(-bi,-bi,-bj,-bj); entW[p] = float4(w0,w0,w1,w1).
// Inner loop per source pair (rows i0,i1 in the f32x2 lanes => 4 terms):
//   a = den(s0), b = den(s1)   (built from exact integer diffs, 2 roundings)
//   acc += (w0*b + w1*a) * rcp2(a*b)     -> 2 MUFU / 4 terms, full f32
// ~17 issues / 4 terms, unroll 8 with immediate-offset LDS.
// The 2*eps*sqrt(d2) cross term of the reference is dropped
// (relative contribution <= eps/z <= 1e-5 for interior targets).
// ---------------------------------------------------------------------------
__global__ void __launch_bounds__(1024, 1) fused_kernel(
    const float* __restrict__ b, float* __restrict__ out)
{
    extern __shared__ float4 sm[];
    float4* entA = sm;                    // CAPS  float4
    float4* entW = sm + CAPS;             // CAPP  float4
    __shared__ int   cnts[RES];
    __shared__ int   offs[RES];
    __shared__ int   sK;
    __shared__ float red[NWARPS * 64];

    const int tid  = threadIdx.x;
    const int wid  = tid >> 5;
    const int lane = tid & 31;

    // ---- Phase 0: zero packed arrays (pair-tail safety) ----
    for (int t = tid; t < CAPS + CAPP; t += 1024)
        sm[t] = make_float4(0.f, 0.f, 0.f, 0.f);

    // ---- Phase 1: compaction (row-major deterministic order) ----
    {
        const int r0 = wid * 3;
        #pragma unroll
        for (int rr = 0; rr < 3; rr++) {
            const int row = r0 + rr;
            int c = 0;
            #pragma unroll
            for (int s = 0; s < 3; s++) {
                float v = b[row * RES + s * 32 + lane];
                c += __popc(__ballot_sync(0xffffffffu, v > 0.0f));
            }
            if (lane == 0) cnts[row] = c;
        }
    }
    __syncthreads();
    if (wid == 0) {                       // exclusive prefix over 96 counts
        int a0 = cnts[lane], a1 = cnts[lane + 32], a2 = cnts[lane + 64];
        int s0 = a0, s1 = a1, s2 = a2;
        #pragma unroll
        for (int d = 1; d < 32; d <<= 1) {
            int t0 = __shfl_up_sync(0xffffffffu, s0, d); if (lane >= d) s0 += t0;
            int t1 = __shfl_up_sync(0xffffffffu, s1, d); if (lane >= d) s1 += t1;
            int t2 = __shfl_up_sync(0xffffffffu, s2, d); if (lane >= d) s2 += t2;
        }
        s1 += __shfl_sync(0xffffffffu, s0, 31);
        s2 += __shfl_sync(0xffffffffu, s1, 31);
        offs[lane]      = s0 - a0;
        offs[lane + 32] = s1 - a1;
        offs[lane + 64] = s2 - a2;
        if (lane == 31) sK = s2;
    }
    __syncthreads();
    {
        const int r0 = wid * 3;
        #pragma unroll
        for (int rr = 0; rr < 3; rr++) {
            const int row = r0 + rr;
            int p = offs[row];
            #pragma unroll
            for (int s = 0; s < 3; s++) {
                const int col = s * 32 + lane;
                float v = b[row * RES + col];
                unsigned m = __ballot_sync(0xffffffffu, v > 0.0f);
                if (v > 0.0f) {
                    int pos = p + __popc(m & ((1u << lane) - 1u));
                    entA[pos] = make_float4(-(float)row, -(float)row,
                                            -(float)col, -(float)col);
                    float* wp = reinterpret_cast<float*>(&entW[pos >> 1]);
                    const int o = (pos & 1) * 2;
                    wp[o]     = v;
                    wp[o + 1] = v;
                }
                p += __popc(m);
            }
        }
    }
    __syncthreads();

    // ---- window placement (R3-proven) ----
    const int pp  = blockIdx.x / 3;
    const int g   = blockIdx.x % 3;
    const int i0  = 2 * pp;

    const int a0i = abs(i0 - 48);
    const int a1i = abs(i0 + 1 - 48);
    const int dmin = a0i < a1i ? a0i : a1i;
    int s_ = 2208 - dmin * dmin; if (s_ < 0) s_ = 0;
    const int wmax = (int)sqrtf((float)s_) + 1;   // over-estimate: safe
    int J0 = 48 - wmax; if (J0 < 0) J0 = 0;

    const int j   = J0 + 32 * g + lane;           // may exceed 95 (guarded)
    const float fi0 = (float)i0;
    const float fj  = (float)j;

    const float dic0 = fi0 - CENTERF;
    const float dic1 = dic0 + 1.0f;
    const float djc  = fj - CENTERF;
    const float r2_0 = dic0 * dic0 + djc * djc;   // exact integer-valued
    const float r2_1 = dic1 * dic1 + djc * djc;
    const float z0 = CENTERF - sqrtf(r2_0) + EPSF;
    const float z1 = CENTERF - sqrtf(r2_1) + EPSF;
    const float c00  = fmaf(z0, z0, EPSF * EPSF);
    const float c01v = fmaf(z1, z1, EPSF * EPSF);

    const unsigned long long fi01 = pk2(fi0, fi0 + 1.0f);
    const unsigned long long fj2  = pk2(fj, fj);
    const unsigned long long c01  = pk2(c00, c01v);

    const bool allrim = __all_sync(0xffffffffu,
                                   (r2_0 >= RIM2) && (r2_1 >= RIM2));
    const int K  = sK;
    const int Kp = (K + 1) >> 1;                  // source pairs
    float f0 = 0.0f, f1 = 0.0f;

    // ---- Phase 2: slimmed paired-reciprocal f32x2 core ----
    if (!allrim) {
        unsigned long long acc = pk2(0.0f, 0.0f);
        const int nfull = (Kp > wid) ? (Kp - wid + 31) / 32 : 0;
        const int nb8 = nfull >> 3;
        const float4* pA = entA + 2 * wid;
        const float4* pW = entW + wid;

        for (int b8 = 0; b8 < nb8; b8++) {
            #pragma unroll
            for (int u = 0; u < 8; u++) {
                // LDS.128 with immediate offsets; float4 halves land in pairs
                const float4 eA0 = pA[u * 64];        // (-bi0,-bi0,-bj0,-bj0)
                const float4 eA1 = pA[u * 64 + 1];    // (-bi1,-bi1,-bj1,-bj1)
                const float4 eW  = pW[u * 32];        // ( w0,  w0,  w1,  w1)
                const unsigned long long A0i = pk2(eA0.x, eA0.y);
                const unsigned long long A0j = pk2(eA0.z, eA0.w);
                const unsigned long long A1i = pk2(eA1.x, eA1.y);
                const unsigned long long A1j = pk2(eA1.z, eA1.w);
                const unsigned long long W0  = pk2(eW.x, eW.y);
                const unsigned long long W1  = pk2(eW.z, eW.w);

                unsigned long long di0, dj0, u0, a, di1, dj1, u1, bb;
                ADD2(di0, fi01, A0i);
                ADD2(dj0, fj2,  A0j);
                FMA2(u0, dj0, dj0, c01);
                FMA2(a,  di0, di0, u0);
                ADD2(di1, fi01, A1i);
                ADD2(dj1, fj2,  A1j);
                FMA2(u1, dj1, dj1, c01);
                FMA2(bb, di1, di1, u1);

                unsigned long long P, m, num, inv;
                MUL2(P, a, bb);
                MUL2(m, W0, bb);
                FMA2(num, W1, a, m);
                RCP2(inv, P);
                FMA2(acc, num, inv, acc);
            }
            pA += 512;
            pW += 256;
        }
        for (int r = nb8 * 8; r < nfull; r++) {
            const float4 eA0 = pA[0];
            const float4 eA1 = pA[1];
            const float4 eW  = pW[0];
            pA += 64; pW += 32;
            const unsigned long long A0i = pk2(eA0.x, eA0.y);
            const unsigned long long A0j = pk2(eA0.z, eA0.w);
            const unsigned long long A1i = pk2(eA1.x, eA1.y);
            const unsigned long long A1j = pk2(eA1.z, eA1.w);
            const unsigned long long W0  = pk2(eW.x, eW.y);
            const unsigned long long W1  = pk2(eW.z, eW.w);

            unsigned long long di0, dj0, u0, a, di1, dj1, u1, bb;
            ADD2(di0, fi01, A0i);
            ADD2(dj0, fj2,  A0j);
            FMA2(u0, dj0, dj0, c01);
            FMA2(a,  di0, di0, u0);
            ADD2(di1, fi01, A1i);
            ADD2(dj1, fj2,  A1j);
            FMA2(u1, dj1, dj1, c01);
            FMA2(bb, di1, di1, u1);

            unsigned long long P, m, num, inv;
            MUL2(P, a, bb);
            MUL2(m, W0, bb);
            FMA2(num, W1, a, m);
            RCP2(inv, P);
            FMA2(acc, num, inv, acc);
        }
        unpk2(acc, f0, f1);
    }

    red[wid * 64 + lane]      = f0;
    red[wid * 64 + 32 + lane] = f1;
    __syncthreads();

    // ---- Phase 3: reduce + store ----
    if (tid < 64) {
        const int k = tid >> 5;                   // which of the two i-rows
        const int l = tid & 31;
        float s = 0.0f;
        #pragma unroll
        for (int w = 0; w < NWARPS; w++) s += red[w * 64 + k * 32 + l];

        const int jj = J0 + 32 * g + l;
        if (jj < RES) {
            const int ii  = i0 + k;
            const int di  = ii - 48, dj = jj - 48;
            const float bv = b[ii * RES + jj];
            out[ii * RES + jj] = (di * di + dj * dj >= 2209) ? bv : s;
        }
    }

    // Rim passthrough for uncovered columns j < J0 (provably rim).
    if (g == 0 && tid < RES) {
        if (tid < J0) {
            out[i0 * RES + tid]       = b[i0 * RES + tid];
            out[(i0 + 1) * RES + tid] = b[(i0 + 1) * RES + tid];
        }
    }
}

// ---------------------------------------------------------------------------
extern "C" void kernel_launch(void* const* d_in, const int* in_sizes, int n_in,
                              void* d_out, int out_size) {
    (void)in_sizes; (void)n_in; (void)out_size;
    const float* b   = (const float*)d_in[0];
    float*       out = (float*)d_out;

    const int smem_bytes = (CAPS + CAPP) * (int)sizeof(float4);  // 221184
    cudaFuncSetAttribute(fused_kernel,
                         cudaFuncAttributeMaxDynamicSharedMemorySize, smem_bytes);

    fused_kernel<<<144, 1024, smem_bytes>>>(b, out);
}